// round 5
// baseline (speedup 1.0000x reference)
#include <cuda_runtime.h>
#include <cuda_bf16.h>
#include <cstdint>

// Diagonal linear recurrence with SiLU pre-activation and self-gating.
//   d  = sigmoid(log_d), xa = silu(x)
//   h_t = d*(xa_t + h_{t-1}) + b,  out_t = h_t^2 * sigmoid(h_t)
//
// R3: software-pipelined double buffer. R2 alternated a pure load phase with
// a pure compute phase, so loads were in flight only ~35% of the time
// (measured DRAM=35%). Here tile k+1's 64 independent LDGs are issued before
// tile k's serial chain runs, keeping ~4MB outstanding chip-wide
// continuously. Traffic stays at the 512MB minimum (73us floor @ 7TB/s).

__device__ __forceinline__ float tanh_fast(float x) {
    float y;
    asm("tanh.approx.f32 %0, %1;" : "=f"(y) : "f"(x));
    return y;
}

__device__ __forceinline__ float fast_sigmoid(float x) {
    // sigmoid(x) = 0.5*tanh(0.5x) + 0.5  -> single MUFU.TANH + FMA
    return fmaf(0.5f, tanh_fast(0.5f * x), 0.5f);
}

constexpr int U = 64;   // tile size; two tiles resident -> ~150 regs (1 blk/SM anyway)

__global__ void __launch_bounds__(128, 1)
e54_scan_kernel(const float* __restrict__ x,
                const float* __restrict__ h0,
                const float* __restrict__ log_d,
                const float* __restrict__ bias,
                float* __restrict__ out,
                float* __restrict__ h_final,   // may be nullptr
                int B, int T, int D)
{
    int idx = blockIdx.x * blockDim.x + threadIdx.x;  // lane = b*D + c
    if (idx >= B * D) return;
    int b = idx / D;
    int c = idx - b * D;

    float dc = fast_sigmoid(log_d[c]);
    float bc = bias[c];
    float h  = h0[idx];

    const float* xp = x   + (size_t)b * T * D + c;
    float*       op = out + (size_t)b * T * D + c;

    float bufA[U], bufB[U];

    // Prologue: load tile 0 into A.
    #pragma unroll
    for (int u = 0; u < U; u++) bufA[u] = xp[(size_t)u * D];

    // Steady state: process two tiles per outer iteration (A then B),
    // always issuing the next tile's loads before consuming the current one.
    for (int t0 = 0; t0 < T; t0 += 2 * U) {
        // Issue loads for tile t0+U into B (always in-range: t0+2U <= T).
        #pragma unroll
        for (int u = 0; u < U; u++)
            bufB[u] = xp[(size_t)(t0 + U + u) * D];

        // Compute tile t0 from A (serial chain overlaps B's loads).
        #pragma unroll
        for (int u = 0; u < U; u++) {
            float xv = bufA[u];
            float xa = xv * fast_sigmoid(xv);
            h = fmaf(dc, xa + h, bc);
            float y = h * h * fast_sigmoid(h);
            op[(size_t)(t0 + u) * D] = y;
        }

        // Issue loads for tile t0+2U into A (skip on last iteration).
        if (t0 + 2 * U < T) {
            #pragma unroll
            for (int u = 0; u < U; u++)
                bufA[u] = xp[(size_t)(t0 + 2 * U + u) * D];
        }

        // Compute tile t0+U from B (overlaps A's loads).
        #pragma unroll
        for (int u = 0; u < U; u++) {
            float xv = bufB[u];
            float xa = xv * fast_sigmoid(xv);
            h = fmaf(dc, xa + h, bc);
            float y = h * h * fast_sigmoid(h);
            op[(size_t)(t0 + U + u) * D] = y;
        }
    }

    if (h_final) h_final[idx] = h;
}

extern "C" void kernel_launch(void* const* d_in, const int* in_sizes, int n_in,
                              void* d_out, int out_size)
{
    const float* x     = (const float*)d_in[0];
    const float* h0    = (const float*)d_in[1];
    const float* log_d = (const float*)d_in[2];
    const float* bias  = (const float*)d_in[3];
    float* out = (float*)d_out;

    int D  = in_sizes[2];
    int BD = in_sizes[1];
    int B  = BD / D;
    int T  = in_sizes[0] / BD;

    long long main_elems = (long long)B * T * D;
    float* h_final = nullptr;
    if ((long long)out_size >= main_elems + BD) {
        h_final = out + main_elems;   // harness concatenates (output, h_final)
    }

    int threads = 128;
    int blocks  = (BD + threads - 1) / threads;
    e54_scan_kernel<<<blocks, threads>>>(x, h0, log_d, bias, out, h_final, B, T, D);
}

// round 6
// speedup vs baseline: 1.5455x; 1.5455x over previous
#include <cuda_runtime.h>
#include <cuda_bf16.h>
#include <cstdint>

// Diagonal linear recurrence with SiLU pre-activation and self-gating.
//   d = sigmoid(log_d);  h_t = d*(silu(x_t) + h_{t-1}) + b;  out = h^2*sigmoid(h)
//
// R4: chunked parallel scan. The recurrence is affine with constant per-channel
// multiplier d, so a length-L chunk composes as h_end = d^L*h_start + A.
// Block = 8 lanes x 64 chunks (512 thr); each thread holds its 64 x-values in
// REGISTERS (x read exactly once -> 512MB total traffic), computes the chunk
// aggregate, a 6-step Kogge-Stone weighted scan over chunks produces start
// states, then the chunk replays from registers to emit outputs.
// Parallelism: 32768 warps (vs 512 in the pure serial form) -> BW-bound.

__device__ __forceinline__ float tanh_fast(float x) {
    float y;
    asm("tanh.approx.f32 %0, %1;" : "=f"(y) : "f"(x));
    return y;
}

__device__ __forceinline__ float fast_sigmoid(float x) {
    // sigmoid(x) = 0.5*tanh(0.5x) + 0.5  -> single MUFU.TANH + FMA
    return fmaf(0.5f, tanh_fast(0.5f * x), 0.5f);
}

constexpr int L = 64;            // timesteps per thread (register tile)
constexpr int G = 8;             // lanes per block (8 floats = full 32B sectors)
constexpr int C = 64;            // chunks per lane = T/L
constexpr int NTHREADS = G * C;  // 512

__global__ void __launch_bounds__(NTHREADS, 1)
e54_chunked_kernel(const float* __restrict__ x,
                   const float* __restrict__ h0,
                   const float* __restrict__ log_d,
                   const float* __restrict__ bias,
                   float* __restrict__ out,
                   float* __restrict__ h_final,   // may be nullptr
                   int B, int T, int D)
{
    __shared__ float s_state[C * G];

    int t    = threadIdx.x;
    int g    = t & (G - 1);        // lane within block
    int c    = t >> 3;             // chunk index (G=8)
    int lane = blockIdx.x * G + g; // global (b, channel) lane
    int b    = lane / D;
    int ch   = lane - b * D;

    float dc = fast_sigmoid(log_d[ch]);
    float bc = bias[ch];

    const float* xp = x   + (size_t)b * T * D + (size_t)c * L * D + ch;
    float*       op = out + (size_t)b * T * D + (size_t)c * L * D + ch;

    // ---- Load the whole chunk into registers (the only read of x) ----
    float arr[L];
    #pragma unroll
    for (int i = 0; i < L; i++)
        arr[i] = xp[(size_t)i * D];

    // ---- Phase A: silu + local scan with zero initial state ----
    float u = 0.0f;
    #pragma unroll
    for (int i = 0; i < L; i++) {
        float xv = arr[i];
        float xa = xv * fast_sigmoid(xv);
        arr[i] = xa;                      // keep silu(x) for the replay
        u = fmaf(dc, xa + u, bc);
    }
    s_state[c * G + g] = u;               // chunk aggregate A_c

    // P = d^L via 6 squarings (L = 64 = 2^6)
    float P = dc;
    #pragma unroll
    for (int k = 0; k < 6; k++) P *= P;

    // ---- Kogge-Stone weighted inclusive scan over chunks:
    //      S_c = A_c + P*S_{c-1}  =>  S_c = sum_{j<=c} P^(c-j) A_j
    float Pk = P;
    __syncthreads();
    #pragma unroll
    for (int o = 1; o < C; o <<= 1) {
        float r = (c >= o) ? s_state[(c - o) * G + g] : 0.0f;
        __syncthreads();
        if (c >= o)
            s_state[c * G + g] = fmaf(Pk, r, s_state[c * G + g]);
        Pk *= Pk;
        __syncthreads();
    }

    // Start state for this chunk: E_c = P^c * h0 + S_{c-1}
    float Sprev = (c > 0) ? s_state[(c - 1) * G + g] : 0.0f;
    float Pc = 1.0f, Pp = P;
    int cc = c;
    #pragma unroll
    for (int k = 0; k < 6; k++) {
        if (cc & 1) Pc *= Pp;
        Pp *= Pp;
        cc >>= 1;
    }
    float h = fmaf(Pc, h0[lane], Sprev);

    // ---- Phase B: replay chunk from registers with correct start state ----
    #pragma unroll
    for (int i = 0; i < L; i++) {
        h = fmaf(dc, arr[i] + h, bc);
        float y = h * h * fast_sigmoid(h);
        op[(size_t)i * D] = y;
    }

    if (h_final && c == C - 1)
        h_final[lane] = h;
}

// ---------- Fallback (R2 scheme) for unexpected shapes ----------
constexpr int FB_U = 64;

__global__ void __launch_bounds__(128, 1)
e54_serial_kernel(const float* __restrict__ x,
                  const float* __restrict__ h0,
                  const float* __restrict__ log_d,
                  const float* __restrict__ bias,
                  float* __restrict__ out,
                  float* __restrict__ h_final,
                  int B, int T, int D)
{
    int idx = blockIdx.x * blockDim.x + threadIdx.x;
    if (idx >= B * D) return;
    int b = idx / D;
    int c = idx - b * D;

    float dc = fast_sigmoid(log_d[c]);
    float bc = bias[c];
    float h  = h0[idx];

    const float* xp = x   + (size_t)b * T * D + c;
    float*       op = out + (size_t)b * T * D + c;

    int t = 0;
    for (; t + FB_U <= T; t += FB_U) {
        float xv[FB_U];
        #pragma unroll
        for (int u = 0; u < FB_U; u++) xv[u] = xp[(size_t)(t + u) * D];
        #pragma unroll
        for (int u = 0; u < FB_U; u++) xv[u] = xv[u] * fast_sigmoid(xv[u]);
        #pragma unroll
        for (int u = 0; u < FB_U; u++) {
            h = fmaf(dc, xv[u] + h, bc);
            float y = h * h * fast_sigmoid(h);
            op[(size_t)(t + u) * D] = y;
        }
    }
    for (; t < T; t++) {
        float xv = xp[(size_t)t * D];
        float xa = xv * fast_sigmoid(xv);
        h = fmaf(dc, xa + h, bc);
        op[(size_t)t * D] = h * h * fast_sigmoid(h);
    }
    if (h_final) h_final[idx] = h;
}

extern "C" void kernel_launch(void* const* d_in, const int* in_sizes, int n_in,
                              void* d_out, int out_size)
{
    const float* x     = (const float*)d_in[0];
    const float* h0    = (const float*)d_in[1];
    const float* log_d = (const float*)d_in[2];
    const float* bias  = (const float*)d_in[3];
    float* out = (float*)d_out;

    int D  = in_sizes[2];
    int BD = in_sizes[1];
    int B  = BD / D;
    int T  = in_sizes[0] / BD;

    long long main_elems = (long long)B * T * D;
    float* h_final = nullptr;
    if ((long long)out_size >= main_elems + BD) {
        h_final = out + main_elems;   // harness concatenates (output, h_final)
    }

    if (T == L * C && (D % G) == 0 && (BD % G) == 0) {
        int blocks = BD / G;   // 2048
        e54_chunked_kernel<<<blocks, NTHREADS>>>(x, h0, log_d, bias, out,
                                                 h_final, B, T, D);
    } else {
        int threads = 128;
        int blocks  = (BD + threads - 1) / threads;
        e54_serial_kernel<<<blocks, threads>>>(x, h0, log_d, bias, out,
                                               h_final, B, T, D);
    }
}

// round 7
// speedup vs baseline: 1.9862x; 1.2851x over previous
#include <cuda_runtime.h>
#include <cuda_bf16.h>
#include <cstdint>

// Diagonal linear recurrence with SiLU pre-activation and self-gating.
//   d = sigmoid(log_d);  h_t = d*(silu(x_t) + h_{t-1}) + b;  out = h^2*sigmoid(h)
//
// R5: smem-staged chunked scan with cp.async double buffering.
//  - Block owns 32 CONSECUTIVE channels -> every gmem access is a full 128B
//    line (R4's G=8 layout split each LDG across 4 lines; L1 was 62% busy).
//  - x streamed through 2x16KB smem tiles via cp.async.cg, prefetch distance
//    1 -> loads in flight during compute (R2's phase-alternation fixed).
//  - Per 128-step tile: 32 chunk-warps do L=4 local scans; warp 0 composes
//    the 32 chunk aggregates serially (exact affine composition, carries
//    inter-tile state in registers); replay + coalesced stores.
//  - 40KB static smem, ~45 regs -> 2 blocks/SM, occ ~90% (vs 24% in R4).

__device__ __forceinline__ float tanh_fast(float x) {
    float y;
    asm("tanh.approx.f32 %0, %1;" : "=f"(y) : "f"(x));
    return y;
}

__device__ __forceinline__ float fast_sigmoid(float x) {
    // sigmoid(x) = 0.5*tanh(0.5x) + 0.5  -> single MUFU.TANH + FMA
    return fmaf(0.5f, tanh_fast(0.5f * x), 0.5f);
}

__device__ __forceinline__ void cp_async16(void* smem_dst, const void* gmem_src) {
    uint32_t s;
    asm("{ .reg .u64 a; cvta.to.shared.u64 a, %0; cvt.u32.u64 %1, a; }"
        :: "l"(smem_dst), "r"(s));
    // (two-step to keep it simple & portable)
    asm volatile("{ .reg .u64 a; cvta.to.shared.u64 a, %1; .reg .u32 b; cvt.u32.u64 b, a;"
                 "  cp.async.cg.shared.global [b], [%0], 16; }"
                 :: "l"(gmem_src), "l"(smem_dst) : "memory");
}

constexpr int CH    = 32;    // channels per block (one 128B line)
constexpr int CK    = 32;    // chunk-warps per block
constexpr int LL    = 4;     // timesteps per chunk per tile
constexpr int TILE  = CK * LL;          // 128 timesteps per tile
constexpr int NT    = CH * CK;          // 1024 threads

__global__ void __launch_bounds__(NT, 2)
e54_smem_kernel(const float* __restrict__ x,
                const float* __restrict__ h0,
                const float* __restrict__ log_d,
                const float* __restrict__ bias,
                float* __restrict__ out,
                float* __restrict__ h_final,   // may be nullptr
                int B, int T, int D)
{
    __shared__ float buf[2][TILE * CH];     // 2 x 16KB
    __shared__ float aggr[CK * CH];         // chunk aggregates
    __shared__ float estart[CK * CH];       // chunk start states

    const int tid = threadIdx.x;
    const int ch  = tid & (CH - 1);         // channel within block
    const int c   = tid >> 5;               // chunk index == warp id

    const int  base = blockIdx.x * CH;      // first global lane of this block
    const int  b    = base / D;             // 32 | D -> whole block same batch
    const int  ch0  = base - b * D;
    const int  lane = base + ch;            // global (b,channel) lane
    const int  chg  = ch0 + ch;             // global channel

    const float dc = fast_sigmoid(log_d[chg]);
    const float bc = bias[chg];
    const float d2 = dc * dc;
    const float P  = d2 * d2;               // d^LL  (LL = 4)

    // Inter-tile carry lives in warp 0's registers.
    float hcar = (c == 0) ? h0[lane] : 0.0f;

    // Loader role: one float4 per thread per tile, fully coalesced rows.
    const int q = tid & 7;                  // quad within 128B row
    const int r = tid >> 3;                 // row (timestep) 0..127
    const float* xrow = x + (size_t)b * T * D + ch0;

    const int ntiles = T / TILE;

    // Prologue: load tile 0.
    cp_async16(&buf[0][r * CH + q * 4], xrow + (size_t)r * D + q * 4);
    asm volatile("cp.async.commit_group;" ::: "memory");

    for (int j = 0; j < ntiles; j++) {
        const int cur = j & 1;

        // Prefetch tile j+1 into the other buffer (overlaps this tile's math).
        if (j + 1 < ntiles) {
            cp_async16(&buf[cur ^ 1][r * CH + q * 4],
                       xrow + (size_t)((j + 1) * TILE + r) * D + q * 4);
        }
        asm volatile("cp.async.commit_group;" ::: "memory");
        asm volatile("cp.async.wait_group 1;" ::: "memory");  // tile j ready
        __syncthreads();

        // ---- Phase A: silu + local scan (h=0), silu kept in registers ----
        float sv[LL];
        float u = 0.0f;
        #pragma unroll
        for (int i = 0; i < LL; i++) {
            float xv = buf[cur][(c * LL + i) * CH + ch];
            float xa = xv * fast_sigmoid(xv);
            sv[i] = xa;
            u = fmaf(dc, xa + u, bc);
        }
        aggr[c * CH + ch] = u;
        __syncthreads();

        // ---- Warp 0: exact serial affine composition over 32 chunks ----
        if (c == 0) {
            float s = hcar;
            #pragma unroll
            for (int k = 0; k < CK; k++) {
                estart[k * CH + ch] = s;
                s = fmaf(P, s, aggr[k * CH + ch]);   // h_end = d^L*h + A
            }
            hcar = s;                                 // carry to next tile
        }
        __syncthreads();

        // ---- Phase B: replay with correct start state, gated store ----
        float h = estart[c * CH + ch];
        float* orow = out + (size_t)b * T * D + (size_t)(j * TILE + c * LL) * D + chg;
        #pragma unroll
        for (int i = 0; i < LL; i++) {
            h = fmaf(dc, sv[i] + h, bc);
            float y = h * h * fast_sigmoid(h);
            orow[(size_t)i * D] = y;                 // warp = one 128B line
        }
        __syncthreads();   // buffer cur^1 consumed next iter; cur rewritten in j+2
    }

    if (h_final && c == 0)
        h_final[lane] = hcar;
}

// ---------- Fallback (R2 scheme) for unexpected shapes ----------
constexpr int FB_U = 64;

__global__ void __launch_bounds__(128, 1)
e54_serial_kernel(const float* __restrict__ x,
                  const float* __restrict__ h0,
                  const float* __restrict__ log_d,
                  const float* __restrict__ bias,
                  float* __restrict__ out,
                  float* __restrict__ h_final,
                  int B, int T, int D)
{
    int idx = blockIdx.x * blockDim.x + threadIdx.x;
    if (idx >= B * D) return;
    int b = idx / D;
    int c = idx - b * D;

    float dc = fast_sigmoid(log_d[c]);
    float bc = bias[c];
    float h  = h0[idx];

    const float* xp = x   + (size_t)b * T * D + c;
    float*       op = out + (size_t)b * T * D + c;

    int t = 0;
    for (; t + FB_U <= T; t += FB_U) {
        float xv[FB_U];
        #pragma unroll
        for (int u = 0; u < FB_U; u++) xv[u] = xp[(size_t)(t + u) * D];
        #pragma unroll
        for (int u = 0; u < FB_U; u++) xv[u] = xv[u] * fast_sigmoid(xv[u]);
        #pragma unroll
        for (int u = 0; u < FB_U; u++) {
            h = fmaf(dc, xv[u] + h, bc);
            float y = h * h * fast_sigmoid(h);
            op[(size_t)(t + u) * D] = y;
        }
    }
    for (; t < T; t++) {
        float xv = xp[(size_t)t * D];
        float xa = xv * fast_sigmoid(xv);
        h = fmaf(dc, xa + h, bc);
        op[(size_t)t * D] = h * h * fast_sigmoid(h);
    }
    if (h_final) h_final[idx] = h;
}

extern "C" void kernel_launch(void* const* d_in, const int* in_sizes, int n_in,
                              void* d_out, int out_size)
{
    const float* x     = (const float*)d_in[0];
    const float* h0    = (const float*)d_in[1];
    const float* log_d = (const float*)d_in[2];
    const float* bias  = (const float*)d_in[3];
    float* out = (float*)d_out;

    int D  = in_sizes[2];
    int BD = in_sizes[1];
    int B  = BD / D;
    int T  = in_sizes[0] / BD;

    long long main_elems = (long long)B * T * D;
    float* h_final = nullptr;
    if ((long long)out_size >= main_elems + BD) {
        h_final = out + main_elems;   // harness concatenates (output, h_final)
    }

    if ((T % TILE) == 0 && (D % CH) == 0 && (BD % CH) == 0) {
        int blocks = BD / CH;   // 512
        e54_smem_kernel<<<blocks, NT>>>(x, h0, log_d, bias, out, h_final, B, T, D);
    } else {
        int threads = 128;
        int blocks  = (BD + threads - 1) / threads;
        e54_serial_kernel<<<blocks, threads>>>(x, h0, log_d, bias, out,
                                               h_final, B, T, D);
    }
}